// round 5
// baseline (speedup 1.0000x reference)
// CrossVit_45148696216621 — full self-attention block, fp32 SIMT baseline.
//
// Pipeline (all multiples of 128, no bounds checks needed):
//   1. Q = x@Wq + bq, K = x@Wk + bk, V = x@Wv + bv      (3x GEMM_NN 8192x2048x2048)
//   2. S = Q @ K^T * (1/sqrt(2048))                      (GEMM_NT 8192x8192x2048)
//   3. rowwise softmax(S)                                (memory-bound, row fits in smem)
//   4. out = S @ V                                       (GEMM_NN 8192x2048x8192)
//
// Scratch via __device__ globals (sanctioned; no allocations anywhere).

#include <cuda_runtime.h>
#include <math.h>

#define SEQ 8192
#define EMB 2048

// ---------------------------------------------------------------------------
// Scratch (zero-init .bss-style device globals; ~448 MB total)
// ---------------------------------------------------------------------------
__device__ float g_Q[(size_t)SEQ * EMB];
__device__ float g_K[(size_t)SEQ * EMB];
__device__ float g_V[(size_t)SEQ * EMB];
__device__ float g_S[(size_t)SEQ * SEQ];

// ---------------------------------------------------------------------------
// SGEMM: C[M,N] = alpha * A[M,K] @ op(B) + bias
//   TB=false: B is [K,N] row-major (NN)
//   TB=true : B is [N,K] row-major (NT, i.e. C = A @ B^T)
// Block tile 128x128, K-tile 8, 256 threads, 8x8 per-thread micro-tile.
// M,N,K must be multiples of 128 / 8 (true for all call sites).
// ---------------------------------------------------------------------------
template <bool TB>
__global__ __launch_bounds__(256, 2)
void sgemm_kernel(const float* __restrict__ A,
                  const float* __restrict__ B,
                  float* __restrict__ C,
                  int M, int N, int K,
                  const float* __restrict__ bias,
                  float alpha)
{
    __shared__ float As[8][128];   // As[k][m]
    __shared__ float Bs[8][128];   // Bs[k][n]

    const int tid = threadIdx.x;
    const int bx = blockIdx.x;     // N-tile index
    const int by = blockIdx.y;     // M-tile index

    const int ty = tid >> 4;       // 0..15  -> micro-tile row group
    const int tx = tid & 15;       // 0..15  -> micro-tile col group

    float acc[8][8];
#pragma unroll
    for (int i = 0; i < 8; i++)
#pragma unroll
        for (int j = 0; j < 8; j++) acc[i][j] = 0.0f;

    // A tile loader: each thread loads one float4.
    // row = tid>>1 (0..127), k-col = (tid&1)*4
    const int aRow = tid >> 1;
    const int aCol = (tid & 1) * 4;
    const float* Aptr = A + (size_t)(by * 128 + aRow) * K + aCol;

    // B tile loader
    int bRow, bCol;
    const float* Bptr;
    if (TB) {
        // B is [N,K]: load like A (row = n within tile, col = k)
        bRow = tid >> 1;            // 0..127 (n)
        bCol = (tid & 1) * 4;       // k
        Bptr = B + (size_t)(bx * 128 + bRow) * K + bCol;
    } else {
        // B is [K,N]: 8 rows x 128 cols, row = k, col = n
        bRow = tid >> 5;            // 0..7 (k)
        bCol = (tid & 31) * 4;      // 0..124 (n)
        Bptr = B + (size_t)bRow * N + (size_t)bx * 128 + bCol;
    }

    for (int k0 = 0; k0 < K; k0 += 8) {
        // Global loads into registers first
        const float4 av = *(const float4*)(Aptr + k0);
        float4 bv;
        if (TB) bv = *(const float4*)(Bptr + k0);
        else    bv = *(const float4*)(Bptr + (size_t)k0 * N);

        __syncthreads();   // previous compute done before smem overwrite

        // Store A transposed: As[k][m]
        As[aCol + 0][aRow] = av.x;
        As[aCol + 1][aRow] = av.y;
        As[aCol + 2][aRow] = av.z;
        As[aCol + 3][aRow] = av.w;

        if (TB) {
            Bs[bCol + 0][bRow] = bv.x;
            Bs[bCol + 1][bRow] = bv.y;
            Bs[bCol + 2][bRow] = bv.z;
            Bs[bCol + 3][bRow] = bv.w;
        } else {
            *(float4*)&Bs[bRow][bCol] = bv;
        }

        __syncthreads();

#pragma unroll
        for (int kk = 0; kk < 8; kk++) {
            const float4 a0 = *(const float4*)&As[kk][ty * 8];
            const float4 a1 = *(const float4*)&As[kk][ty * 8 + 4];
            const float4 b0 = *(const float4*)&Bs[kk][tx * 8];
            const float4 b1 = *(const float4*)&Bs[kk][tx * 8 + 4];
            const float ar[8] = {a0.x, a0.y, a0.z, a0.w, a1.x, a1.y, a1.z, a1.w};
            const float br[8] = {b0.x, b0.y, b0.z, b0.w, b1.x, b1.y, b1.z, b1.w};
#pragma unroll
            for (int i = 0; i < 8; i++)
#pragma unroll
                for (int j = 0; j < 8; j++)
                    acc[i][j] = fmaf(ar[i], br[j], acc[i][j]);
        }
    }

    // Epilogue: alpha scale + optional bias, float4 stores
    const int row0 = by * 128 + ty * 8;
    const int col0 = bx * 128 + tx * 8;

    float bb[8];
#pragma unroll
    for (int j = 0; j < 8; j++) bb[j] = bias ? bias[col0 + j] : 0.0f;

#pragma unroll
    for (int i = 0; i < 8; i++) {
        float4 v0, v1;
        v0.x = acc[i][0] * alpha + bb[0];
        v0.y = acc[i][1] * alpha + bb[1];
        v0.z = acc[i][2] * alpha + bb[2];
        v0.w = acc[i][3] * alpha + bb[3];
        v1.x = acc[i][4] * alpha + bb[4];
        v1.y = acc[i][5] * alpha + bb[5];
        v1.z = acc[i][6] * alpha + bb[6];
        v1.w = acc[i][7] * alpha + bb[7];
        float* cptr = C + (size_t)(row0 + i) * N + col0;
        *(float4*)(cptr)     = v0;
        *(float4*)(cptr + 4) = v1;
    }
}

// ---------------------------------------------------------------------------
// Row-wise softmax over rows of length SEQ (8192 floats = 32 KB -> fits smem).
// One CTA (256 threads) per row. Numerically-stable (max-subtract).
// ---------------------------------------------------------------------------
__global__ __launch_bounds__(256)
void softmax_rows_kernel(float* __restrict__ S, int n)
{
    __shared__ float buf[SEQ];
    __shared__ float red[256];

    const int tid = threadIdx.x;
    float* p = S + (size_t)blockIdx.x * n;

    // Load row + local max
    float m = -INFINITY;
    for (int i = tid; i < n; i += 256) {
        const float v = p[i];
        buf[i] = v;
        m = fmaxf(m, v);
    }
    red[tid] = m;
    __syncthreads();
#pragma unroll
    for (int s = 128; s > 0; s >>= 1) {
        if (tid < s) red[tid] = fmaxf(red[tid], red[tid + s]);
        __syncthreads();
    }
    m = red[0];
    __syncthreads();   // everyone has read red[0] before reuse

    // exp + local sum
    float sum = 0.0f;
    for (int i = tid; i < n; i += 256) {
        const float e = expf(buf[i] - m);
        buf[i] = e;
        sum += e;
    }
    red[tid] = sum;
    __syncthreads();
#pragma unroll
    for (int s = 128; s > 0; s >>= 1) {
        if (tid < s) red[tid] += red[tid + s];
        __syncthreads();
    }
    const float inv = 1.0f / red[0];

    // Normalize + write back
    for (int i = tid; i < n; i += 256)
        p[i] = buf[i] * inv;
}

// ---------------------------------------------------------------------------
// Launch
// ---------------------------------------------------------------------------
extern "C" void kernel_launch(void* const* d_in, const int* in_sizes, int n_in,
                              void* d_out, int out_size)
{
    (void)in_sizes; (void)n_in; (void)out_size;

    const float* x  = (const float*)d_in[0];
    const float* Wq = (const float*)d_in[1];
    const float* bq = (const float*)d_in[2];
    const float* Wk = (const float*)d_in[3];
    const float* bk = (const float*)d_in[4];
    const float* Wv = (const float*)d_in[5];
    const float* bv = (const float*)d_in[6];
    float* out = (float*)d_out;

    // Resolve scratch symbol addresses once (cached -> capture call is
    // pure kernel launches; deterministic, no work skipped).
    static float *Qp = nullptr, *Kp = nullptr, *Vp = nullptr, *Sp = nullptr;
    if (!Qp) {
        cudaGetSymbolAddress((void**)&Qp, g_Q);
        cudaGetSymbolAddress((void**)&Kp, g_K);
        cudaGetSymbolAddress((void**)&Vp, g_V);
        cudaGetSymbolAddress((void**)&Sp, g_S);
    }

    const dim3 blk(256);
    const dim3 gProj(EMB / 128, SEQ / 128);   // (16, 64)
    const dim3 gScore(SEQ / 128, SEQ / 128);  // (64, 64)

    // 1. QKV projections (bias fused into epilogue)
    sgemm_kernel<false><<<gProj, blk>>>(x, Wq, Qp, SEQ, EMB, EMB, bq, 1.0f);
    sgemm_kernel<false><<<gProj, blk>>>(x, Wk, Kp, SEQ, EMB, EMB, bk, 1.0f);
    sgemm_kernel<false><<<gProj, blk>>>(x, Wv, Vp, SEQ, EMB, EMB, bv, 1.0f);

    // 2. S = Q @ K^T * 1/sqrt(EMB)
    const float scale = 1.0f / sqrtf((float)EMB);
    sgemm_kernel<true><<<gScore, blk>>>(Qp, Kp, Sp, SEQ, SEQ, EMB, nullptr, scale);

    // 3. softmax rows
    softmax_rows_kernel<<<SEQ, blk>>>(Sp, SEQ);

    // 4. out = P @ V
    sgemm_kernel<false><<<gProj, blk>>>(Sp, Vp, out, SEQ, EMB, SEQ, nullptr, 1.0f);
}

// round 10
// speedup vs baseline: 3.2857x; 3.2857x over previous
// CrossVit — bf16-split (3-term) attention block on mma.sync (sm_100-safe).
// x ≈ xh + xl (bf16 hi/lo); A@B ≈ AhBh + AhBl + AlBh (fp32 accum).
// GEMM: CTA 128x128, KT=64, swizzled smem, 2-stage cp.async pipeline,
// 8 warps x (64x32) warp tiles, mma.sync.m16n8k16.bf16. A[M,K] @ B[N,K]^T.
#include <cuda_runtime.h>
#include <cuda_bf16.h>
#include <math.h>
#include <stdint.h>

#define SEQ 8192
#define EMB 2048
#define MT 128
#define NTB 128
#define KT 64
#define OFF_AL 16384
#define OFF_BH 32768
#define OFF_BL 49152
#define STAGE_BYTES 65536
#define DYN_SMEM (2 * STAGE_BYTES)   // 128 KB

typedef __nv_bfloat16 bf16;

__device__ __align__(256) bf16 g_xh[(size_t)SEQ * EMB];
__device__ __align__(256) bf16 g_xl[(size_t)SEQ * EMB];
__device__ __align__(256) bf16 g_wh[3][(size_t)EMB * EMB];
__device__ __align__(256) bf16 g_wl[3][(size_t)EMB * EMB];
__device__ __align__(256) bf16 g_qh[(size_t)SEQ * EMB];
__device__ __align__(256) bf16 g_ql[(size_t)SEQ * EMB];
__device__ __align__(256) bf16 g_kh[(size_t)SEQ * EMB];
__device__ __align__(256) bf16 g_kl[(size_t)SEQ * EMB];
__device__ __align__(256) bf16 g_vth[(size_t)EMB * SEQ];
__device__ __align__(256) bf16 g_vtl[(size_t)EMB * SEQ];
__device__ __align__(256) float g_S[(size_t)SEQ * SEQ];   // also V-proj fp32 tmp
__device__ __align__(256) bf16 g_ph[(size_t)SEQ * SEQ];
__device__ __align__(256) bf16 g_pl[(size_t)SEQ * SEQ];

__device__ __forceinline__ uint32_t s2u(const void* p) {
    uint32_t a;
    asm("{ .reg .u64 t; cvta.to.shared.u64 t, %1; cvt.u32.u64 %0, t; }" : "=r"(a) : "l"(p));
    return a;
}
__device__ __forceinline__ void cp16(uint32_t d, const void* g) {
    asm volatile("cp.async.cg.shared.global [%0], [%1], 16;"
                 :: "r"(d), "l"(__cvta_generic_to_global(g)) : "memory");
}
#define CP_COMMIT()  asm volatile("cp.async.commit_group;" ::: "memory")
#define CP_WAIT(n)   asm volatile("cp.async.wait_group %0;" :: "n"(n) : "memory")
#define LDM4(r, addr) \
    asm volatile("ldmatrix.sync.aligned.m8n8.x4.shared.b16 {%0,%1,%2,%3}, [%4];" \
        : "=r"((r)[0]), "=r"((r)[1]), "=r"((r)[2]), "=r"((r)[3]) : "r"(addr))
#define MMA(c, a, b) \
    asm volatile("mma.sync.aligned.m16n8k16.row.col.f32.bf16.bf16.f32 " \
        "{%0,%1,%2,%3}, {%4,%5,%6,%7}, {%8,%9}, {%0,%1,%2,%3};" \
        : "+f"((c)[0]), "+f"((c)[1]), "+f"((c)[2]), "+f"((c)[3]) \
        : "r"((a)[0]), "r"((a)[1]), "r"((a)[2]), "r"((a)[3]), "r"((b)[0]), "r"((b)[1]))

// Stage loader: A/B hi+lo, 128 rows x 8 x 16B chunks each, swizzled.
__device__ __forceinline__ void load_stage(
    uint32_t sb, int stage, int tid, size_t m0, size_t n0, int k0, int K,
    const bf16* Ah, const bf16* Al, const bf16* Bh, const bf16* Bl)
{
    const uint32_t tb = sb + stage * STAGE_BYTES;
    #pragma unroll
    for (int it = 0; it < 4; it++) {
        const int t = tid + it * 256;
        const int rw = t >> 3, c = t & 7;
        const uint32_t d = tb + rw * 128 + ((c ^ (rw & 7)) << 4);
        const size_t offa = (m0 + rw) * (size_t)K + k0 + c * 8;
        const size_t offb = (n0 + rw) * (size_t)K + k0 + c * 8;
        cp16(d, Ah + offa);          cp16(d + OFF_AL, Al + offa);
        cp16(d + OFF_BH, Bh + offb); cp16(d + OFF_BL, Bl + offb);
    }
}

// C = A @ B^T. A:[M,K] hi/lo, B:[N,K] hi/lo, K-major bf16, K % 64 == 0.
// MODE 0: fp32 out = acc*alpha (+bias). MODE 1: split bf16 out (+bias).
template <int MODE>
__global__ __launch_bounds__(256, 1)
void gemm3(const bf16* __restrict__ Ah, const bf16* __restrict__ Al,
           const bf16* __restrict__ Bh, const bf16* __restrict__ Bl,
           int Ncols, int K, const float* __restrict__ bias, float alpha,
           float* __restrict__ Cf, bf16* __restrict__ Ch, bf16* __restrict__ Cl)
{
    extern __shared__ __align__(1024) char smem[];
    const uint32_t sb = s2u(smem);
    const int tid = threadIdx.x;
    const int wid = tid >> 5, lane = tid & 31;
    const int num_n = Ncols / NTB;
    const int per = 8 * num_n;                 // group 8 M-tiles for L2 reuse
    const int bm = (blockIdx.x / per) * 8 + (blockIdx.x % per) % 8;
    const int bn = (blockIdx.x % per) / 8;
    const size_t m0 = (size_t)bm * MT, n0 = (size_t)bn * NTB;

    const int wm = (wid & 1) * 64;             // warp M offset (2 warps)
    const int wn = (wid >> 1) * 32;            // warp N offset (4 warps)

    // ldmatrix lane geometry (canonical m16n8k16 fragments)
    const int arow  = (lane & 7) + ((lane >> 3) & 1) * 8;
    const int acolb = ((lane >> 4) & 1) * 16;
    const int brow  = (lane & 7) + ((lane >> 4) & 1) * 8;
    const int bcolb = ((lane >> 3) & 1) * 16;
    uint32_t aoff[4], axor[4], boff[2], bxor[2];
    #pragma unroll
    for (int mf = 0; mf < 4; mf++) {
        const int r = wm + mf * 16 + arow;
        aoff[mf] = r * 128; axor[mf] = (r & 7) << 4;
    }
    #pragma unroll
    for (int p = 0; p < 2; p++) {
        const int r = wn + p * 16 + brow;
        boff[p] = r * 128; bxor[p] = (r & 7) << 4;
    }

    float acc[4][4][4];
    #pragma unroll
    for (int i = 0; i < 4; i++)
        #pragma unroll
        for (int j = 0; j < 4; j++)
            #pragma unroll
            for (int q = 0; q < 4; q++) acc[i][j][q] = 0.f;

    const int nk = K / KT;
    load_stage(sb, 0, tid, m0, n0, 0, K, Ah, Al, Bh, Bl);
    CP_COMMIT();
    for (int ch = 0; ch < nk; ch++) {
        if (ch + 1 < nk) {
            load_stage(sb, (ch + 1) & 1, tid, m0, n0, (ch + 1) * KT, K, Ah, Al, Bh, Bl);
            CP_COMMIT(); CP_WAIT(1);
        } else {
            CP_WAIT(0);
        }
        __syncthreads();
        const uint32_t tb = sb + (ch & 1) * STAGE_BYTES;
        #pragma unroll
        for (int ks = 0; ks < 4; ks++) {
            const int kb = ks * 32;
            uint32_t ah[4][4], al[4][4], bh[4][2], bl[4][2];
            #pragma unroll
            for (int mf = 0; mf < 4; mf++) {
                const uint32_t ad = tb + aoff[mf] + ((kb + acolb) ^ axor[mf]);
                LDM4(ah[mf], ad);
                LDM4(al[mf], ad + OFF_AL);
            }
            #pragma unroll
            for (int p = 0; p < 2; p++) {
                const uint32_t bd = tb + OFF_BH + boff[p] + ((kb + bcolb) ^ bxor[p]);
                uint32_t r4[4];
                LDM4(r4, bd);
                bh[2*p][0] = r4[0]; bh[2*p][1] = r4[1];
                bh[2*p+1][0] = r4[2]; bh[2*p+1][1] = r4[3];
                LDM4(r4, bd + (OFF_BL - OFF_BH));
                bl[2*p][0] = r4[0]; bl[2*p][1] = r4[1];
                bl[2*p+1][0] = r4[2]; bl[2*p+1][1] = r4[3];
            }
            #pragma unroll
            for (int mf = 0; mf < 4; mf++)
                #pragma unroll
                for (int nf = 0; nf < 4; nf++) {
                    MMA(acc[mf][nf], ah[mf], bh[nf]);
                    MMA(acc[mf][nf], ah[mf], bl[nf]);
                    MMA(acc[mf][nf], al[mf], bh[nf]);
                }
        }
        __syncthreads();
    }

    // Epilogue from registers. c0,c1 -> row g; c2,c3 -> row g+8.
    const int gq = lane >> 2, tg = lane & 3;
    #pragma unroll
    for (int mf = 0; mf < 4; mf++)
        #pragma unroll
        for (int nf = 0; nf < 4; nf++) {
            const size_t row = m0 + wm + mf * 16 + gq;
            const int col = (int)n0 + wn + nf * 8 + tg * 2;
            const float b0 = bias ? bias[col] : 0.f;
            const float b1 = bias ? bias[col + 1] : 0.f;
            if (MODE == 0) {
                float2 v0, v1;
                v0.x = acc[mf][nf][0] * alpha + b0;
                v0.y = acc[mf][nf][1] * alpha + b1;
                v1.x = acc[mf][nf][2] * alpha + b0;
                v1.y = acc[mf][nf][3] * alpha + b1;
                *(float2*)(Cf + row * (size_t)Ncols + col) = v0;
                *(float2*)(Cf + (row + 8) * (size_t)Ncols + col) = v1;
            } else {
                #pragma unroll
                for (int h = 0; h < 2; h++) {
                    const float v0 = acc[mf][nf][2*h]     + b0;
                    const float v1 = acc[mf][nf][2*h + 1] + b1;
                    const bf16 h0 = __float2bfloat16(v0), h1 = __float2bfloat16(v1);
                    __nv_bfloat162 hp; hp.x = h0; hp.y = h1;
                    __nv_bfloat162 lp;
                    lp.x = __float2bfloat16(v0 - __bfloat162float(h0));
                    lp.y = __float2bfloat16(v1 - __bfloat162float(h1));
                    const size_t o = (row + 8 * h) * (size_t)Ncols + col;
                    *(__nv_bfloat162*)(Ch + o) = hp;
                    *(__nv_bfloat162*)(Cl + o) = lp;
                }
            }
        }
}

__global__ void split_kernel(const float* __restrict__ in, bf16* __restrict__ hi,
                             bf16* __restrict__ lo, size_t n)
{
    for (size_t i = blockIdx.x * (size_t)blockDim.x + threadIdx.x; i < n;
         i += (size_t)gridDim.x * blockDim.x) {
        const float v = in[i];
        const bf16 h = __float2bfloat16(v);
        hi[i] = h;
        lo[i] = __float2bfloat16(v - __bfloat162float(h));
    }
}

// out[c][r] = split(in[r][c]); in [R,C] fp32 -> out [C,R] bf16 hi/lo.
__global__ __launch_bounds__(256)
void splitT_kernel(const float* __restrict__ in, bf16* __restrict__ hi,
                   bf16* __restrict__ lo, int R, int C)
{
    __shared__ float t[32][33];
    const int c0 = blockIdx.x * 32, r0 = blockIdx.y * 32;
    const int x = threadIdx.x & 31, y = threadIdx.x >> 5;
    #pragma unroll
    for (int j = 0; j < 32; j += 8)
        t[y + j][x] = in[(size_t)(r0 + y + j) * C + c0 + x];
    __syncthreads();
    #pragma unroll
    for (int j = 0; j < 32; j += 8) {
        const float v = t[x][y + j];
        const bf16 h = __float2bfloat16(v);
        const size_t o = (size_t)(c0 + y + j) * R + r0 + x;
        hi[o] = h;
        lo[o] = __float2bfloat16(v - __bfloat162float(h));
    }
}

__global__ __launch_bounds__(256)
void softmax_split_kernel(const float* __restrict__ S, bf16* __restrict__ Ph,
                          bf16* __restrict__ Pl)
{
    __shared__ float buf[SEQ];
    __shared__ float red[256];
    const int tid = threadIdx.x;
    const float* p = S + (size_t)blockIdx.x * SEQ;
    float m = -INFINITY;
    for (int i = tid; i < SEQ; i += 256) { buf[i] = p[i]; m = fmaxf(m, p[i]); }
    red[tid] = m; __syncthreads();
    #pragma unroll
    for (int s = 128; s > 0; s >>= 1) {
        if (tid < s) red[tid] = fmaxf(red[tid], red[tid + s]);
        __syncthreads();
    }
    m = red[0]; __syncthreads();
    float sum = 0.f;
    for (int i = tid; i < SEQ; i += 256) {
        const float e = expf(buf[i] - m); buf[i] = e; sum += e;
    }
    red[tid] = sum; __syncthreads();
    #pragma unroll
    for (int s = 128; s > 0; s >>= 1) {
        if (tid < s) red[tid] += red[tid + s];
        __syncthreads();
    }
    const float inv = 1.f / red[0];
    bf16* ph = Ph + (size_t)blockIdx.x * SEQ;
    bf16* pl = Pl + (size_t)blockIdx.x * SEQ;
    for (int i = tid; i < SEQ; i += 256) {
        const float v = buf[i] * inv;
        const bf16 h = __float2bfloat16(v);
        ph[i] = h;
        pl[i] = __float2bfloat16(v - __bfloat162float(h));
    }
}

extern "C" void kernel_launch(void* const* d_in, const int* in_sizes, int n_in,
                              void* d_out, int out_size)
{
    (void)in_sizes; (void)n_in; (void)out_size;
    const float* x  = (const float*)d_in[0];
    const float* W[3] = {(const float*)d_in[1], (const float*)d_in[3], (const float*)d_in[5]};
    const float* bq = (const float*)d_in[2];
    const float* bk = (const float*)d_in[4];
    const float* bv = (const float*)d_in[6];
    float* out = (float*)d_out;

    static bool init = false;
    static bf16 *xh, *xl, *wh[3], *wl[3], *qh, *ql, *kh, *kl, *vth, *vtl, *ph, *pl;
    static float* Sp;
    if (!init) {
        cudaGetSymbolAddress((void**)&xh, g_xh);  cudaGetSymbolAddress((void**)&xl, g_xl);
        bf16 *whb, *wlb;
        cudaGetSymbolAddress((void**)&whb, g_wh); cudaGetSymbolAddress((void**)&wlb, g_wl);
        for (int i = 0; i < 3; i++) { wh[i] = whb + (size_t)i * EMB * EMB;
                                      wl[i] = wlb + (size_t)i * EMB * EMB; }
        cudaGetSymbolAddress((void**)&qh, g_qh);   cudaGetSymbolAddress((void**)&ql, g_ql);
        cudaGetSymbolAddress((void**)&kh, g_kh);   cudaGetSymbolAddress((void**)&kl, g_kl);
        cudaGetSymbolAddress((void**)&vth, g_vth); cudaGetSymbolAddress((void**)&vtl, g_vtl);
        cudaGetSymbolAddress((void**)&Sp, g_S);
        cudaGetSymbolAddress((void**)&ph, g_ph);   cudaGetSymbolAddress((void**)&pl, g_pl);
        cudaFuncSetAttribute(gemm3<0>, cudaFuncAttributeMaxDynamicSharedMemorySize, DYN_SMEM);
        cudaFuncSetAttribute(gemm3<1>, cudaFuncAttributeMaxDynamicSharedMemorySize, DYN_SMEM);
        init = true;
    }

    // 1. split x; split+transpose W (W[K,N] -> Wt[N,K])
    split_kernel<<<1024, 256>>>(x, xh, xl, (size_t)SEQ * EMB);
    for (int i = 0; i < 3; i++)
        splitT_kernel<<<dim3(EMB / 32, EMB / 32), 256>>>(W[i], wh[i], wl[i], EMB, EMB);

    const dim3 gP((SEQ / MT) * (EMB / NTB));   // 1024
    const dim3 gS((SEQ / MT) * (SEQ / NTB));   // 4096
    // 2. Q, K projections -> split bf16 (bias fused)
    gemm3<1><<<gP, 256, DYN_SMEM>>>(xh, xl, wh[0], wl[0], EMB, EMB, bq, 1.f,
                                    nullptr, qh, ql);
    gemm3<1><<<gP, 256, DYN_SMEM>>>(xh, xl, wh[1], wl[1], EMB, EMB, bk, 1.f,
                                    nullptr, kh, kl);
    // 3. V projection -> fp32 tmp, then split+transpose -> Vt[E,S]
    gemm3<0><<<gP, 256, DYN_SMEM>>>(xh, xl, wh[2], wl[2], EMB, EMB, bv, 1.f,
                                    Sp, nullptr, nullptr);
    splitT_kernel<<<dim3(EMB / 32, SEQ / 32), 256>>>(Sp, vth, vtl, SEQ, EMB);
    // 4. S = Q @ K^T * 1/sqrt(E)
    gemm3<0><<<gS, 256, DYN_SMEM>>>(qh, ql, kh, kl, SEQ, EMB, nullptr,
                                    1.f / sqrtf((float)EMB), Sp, nullptr, nullptr);
    // 5. softmax -> P hi/lo
    softmax_split_kernel<<<SEQ, 256>>>(Sp, ph, pl);
    // 6. out = P @ Vt^T  (Vt is [E,S], so B^T = V)
    gemm3<0><<<gP, 256, DYN_SMEM>>>(ph, pl, vth, vtl, EMB, SEQ, nullptr, 1.f,
                                    out, nullptr, nullptr);
}

// round 11
// speedup vs baseline: 8.7676x; 2.6684x over previous
// CrossVit — fp16 single-pass attention block on mma.sync (sm_100-safe).
// fp16 10-bit mantissa => single-pass quantization error ~3e-4 rel,
// compounded ~5e-4 through the chain — inside the 1e-3 gate.
// GEMM: CTA 128x128, KT=64, swizzled smem, 2-stage cp.async, 2 CTAs/SM,
// 8 warps x (64x32) warp tiles, mma.sync.m16n8k16.f16. A[M,K] @ B[N,K]^T.
#include <cuda_runtime.h>
#include <cuda_fp16.h>
#include <math.h>
#include <stdint.h>

#define SEQ 8192
#define EMB 2048
#define MT 128
#define NTB 128
#define KT 64
#define OFF_B 16384
#define STAGE_BYTES 32768
#define DYN_SMEM (2 * STAGE_BYTES)   // 64 KB -> 2 CTAs/SM

typedef __half h16;

__device__ __align__(256) h16 g_x[(size_t)SEQ * EMB];
__device__ __align__(256) h16 g_w[3][(size_t)EMB * EMB];
__device__ __align__(256) h16 g_q[(size_t)SEQ * EMB];
__device__ __align__(256) h16 g_k[(size_t)SEQ * EMB];
__device__ __align__(256) h16 g_vt[(size_t)EMB * SEQ];
__device__ __align__(256) float g_S[(size_t)SEQ * SEQ];   // also V-proj fp32 tmp
__device__ __align__(256) h16 g_p[(size_t)SEQ * SEQ];

__device__ __forceinline__ uint32_t s2u(const void* p) {
    uint32_t a;
    asm("{ .reg .u64 t; cvta.to.shared.u64 t, %1; cvt.u32.u64 %0, t; }" : "=r"(a) : "l"(p));
    return a;
}
__device__ __forceinline__ void cp16(uint32_t d, const void* g) {
    asm volatile("cp.async.cg.shared.global [%0], [%1], 16;"
                 :: "r"(d), "l"(__cvta_generic_to_global(g)) : "memory");
}
#define CP_COMMIT()  asm volatile("cp.async.commit_group;" ::: "memory")
#define CP_WAIT(n)   asm volatile("cp.async.wait_group %0;" :: "n"(n) : "memory")
#define LDM4(r, addr) \
    asm volatile("ldmatrix.sync.aligned.m8n8.x4.shared.b16 {%0,%1,%2,%3}, [%4];" \
        : "=r"((r)[0]), "=r"((r)[1]), "=r"((r)[2]), "=r"((r)[3]) : "r"(addr))
#define MMA(c, a, b) \
    asm volatile("mma.sync.aligned.m16n8k16.row.col.f32.f16.f16.f32 " \
        "{%0,%1,%2,%3}, {%4,%5,%6,%7}, {%8,%9}, {%0,%1,%2,%3};" \
        : "+f"((c)[0]), "+f"((c)[1]), "+f"((c)[2]), "+f"((c)[3]) \
        : "r"((a)[0]), "r"((a)[1]), "r"((a)[2]), "r"((a)[3]), "r"((b)[0]), "r"((b)[1]))

// Stage loader: A + B tiles, 128 rows x 8 x 16B chunks each, swizzled.
__device__ __forceinline__ void load_stage(
    uint32_t sb, int stage, int tid, size_t m0, size_t n0, int k0, int K,
    const h16* A, const h16* B)
{
    const uint32_t tb = sb + stage * STAGE_BYTES;
    #pragma unroll
    for (int it = 0; it < 4; it++) {
        const int t = tid + it * 256;
        const int rw = t >> 3, c = t & 7;
        const uint32_t d = tb + rw * 128 + ((c ^ (rw & 7)) << 4);
        cp16(d,         A + (m0 + rw) * (size_t)K + k0 + c * 8);
        cp16(d + OFF_B, B + (n0 + rw) * (size_t)K + k0 + c * 8);
    }
}

// C = A @ B^T. A:[M,K], B:[N,K], K-major fp16, K % 64 == 0.
// MODE 0: fp32 out = acc*alpha (+bias). MODE 1: fp16 out (+bias).
template <int MODE>
__global__ __launch_bounds__(256, 2)
void gemm1(const h16* __restrict__ A, const h16* __restrict__ B,
           int Ncols, int K, const float* __restrict__ bias, float alpha,
           float* __restrict__ Cf, h16* __restrict__ Ch)
{
    extern __shared__ __align__(1024) char smem[];
    const uint32_t sb = s2u(smem);
    const int tid = threadIdx.x;
    const int wid = tid >> 5, lane = tid & 31;
    const int num_n = Ncols / NTB;
    const int per = 8 * num_n;                 // group 8 M-tiles for L2 reuse
    const int bm = (blockIdx.x / per) * 8 + (blockIdx.x % per) % 8;
    const int bn = (blockIdx.x % per) / 8;
    const size_t m0 = (size_t)bm * MT, n0 = (size_t)bn * NTB;

    const int wm = (wid & 1) * 64;             // warp M offset (2 warps)
    const int wn = (wid >> 1) * 32;            // warp N offset (4 warps)

    // ldmatrix lane geometry (canonical m16n8k16 fragments)
    const int arow  = (lane & 7) + ((lane >> 3) & 1) * 8;
    const int acolb = ((lane >> 4) & 1) * 16;
    const int brow  = (lane & 7) + ((lane >> 4) & 1) * 8;
    const int bcolb = ((lane >> 3) & 1) * 16;
    uint32_t aoff[4], axor[4], boff[2], bxor[2];
    #pragma unroll
    for (int mf = 0; mf < 4; mf++) {
        const int r = wm + mf * 16 + arow;
        aoff[mf] = r * 128; axor[mf] = (r & 7) << 4;
    }
    #pragma unroll
    for (int p = 0; p < 2; p++) {
        const int r = wn + p * 16 + brow;
        boff[p] = r * 128; bxor[p] = (r & 7) << 4;
    }

    float acc[4][4][4];
    #pragma unroll
    for (int i = 0; i < 4; i++)
        #pragma unroll
        for (int j = 0; j < 4; j++)
            #pragma unroll
            for (int q = 0; q < 4; q++) acc[i][j][q] = 0.f;

    const int nk = K / KT;
    load_stage(sb, 0, tid, m0, n0, 0, K, A, B);
    CP_COMMIT();
    for (int ch = 0; ch < nk; ch++) {
        if (ch + 1 < nk) {
            load_stage(sb, (ch + 1) & 1, tid, m0, n0, (ch + 1) * KT, K, A, B);
            CP_COMMIT(); CP_WAIT(1);
        } else {
            CP_WAIT(0);
        }
        __syncthreads();
        const uint32_t tb = sb + (ch & 1) * STAGE_BYTES;
        #pragma unroll
        for (int ks = 0; ks < 4; ks++) {
            const int kb = ks * 32;
            uint32_t ah[4][4], bb[4][2];
            #pragma unroll
            for (int mf = 0; mf < 4; mf++)
                LDM4(ah[mf], tb + aoff[mf] + ((kb + acolb) ^ axor[mf]));
            #pragma unroll
            for (int p = 0; p < 2; p++) {
                uint32_t r4[4];
                LDM4(r4, tb + OFF_B + boff[p] + ((kb + bcolb) ^ bxor[p]));
                bb[2*p][0] = r4[0];   bb[2*p][1] = r4[1];
                bb[2*p+1][0] = r4[2]; bb[2*p+1][1] = r4[3];
            }
            #pragma unroll
            for (int mf = 0; mf < 4; mf++)
                #pragma unroll
                for (int nf = 0; nf < 4; nf++)
                    MMA(acc[mf][nf], ah[mf], bb[nf]);
        }
        __syncthreads();
    }

    // Epilogue from registers. c0,c1 -> row g; c2,c3 -> row g+8.
    const int gq = lane >> 2, tg = lane & 3;
    #pragma unroll
    for (int mf = 0; mf < 4; mf++)
        #pragma unroll
        for (int nf = 0; nf < 4; nf++) {
            const size_t row = m0 + wm + mf * 16 + gq;
            const int col = (int)n0 + wn + nf * 8 + tg * 2;
            const float b0 = bias ? bias[col] : 0.f;
            const float b1 = bias ? bias[col + 1] : 0.f;
            if (MODE == 0) {
                float2 v0, v1;
                v0.x = acc[mf][nf][0] * alpha + b0;
                v0.y = acc[mf][nf][1] * alpha + b1;
                v1.x = acc[mf][nf][2] * alpha + b0;
                v1.y = acc[mf][nf][3] * alpha + b1;
                *(float2*)(Cf + row * (size_t)Ncols + col) = v0;
                *(float2*)(Cf + (row + 8) * (size_t)Ncols + col) = v1;
            } else {
                #pragma unroll
                for (int h = 0; h < 2; h++) {
                    __half2 hp;
                    hp.x = __float2half_rn(acc[mf][nf][2*h]     + b0);
                    hp.y = __float2half_rn(acc[mf][nf][2*h + 1] + b1);
                    *(__half2*)(Ch + (row + 8*h) * (size_t)Ncols + col) = hp;
                }
            }
        }
}

__global__ void cvt_kernel(const float* __restrict__ in, h16* __restrict__ o, size_t n)
{
    for (size_t i = blockIdx.x * (size_t)blockDim.x + threadIdx.x; i < n;
         i += (size_t)gridDim.x * blockDim.x)
        o[i] = __float2half_rn(in[i]);
}

// out[c][r] = fp16(in[r][c]); in [R,C] fp32 -> out [C,R] fp16.
__global__ __launch_bounds__(256)
void cvtT_kernel(const float* __restrict__ in, h16* __restrict__ o, int R, int C)
{
    __shared__ float t[32][33];
    const int c0 = blockIdx.x * 32, r0 = blockIdx.y * 32;
    const int x = threadIdx.x & 31, y = threadIdx.x >> 5;
    #pragma unroll
    for (int j = 0; j < 32; j += 8)
        t[y + j][x] = in[(size_t)(r0 + y + j) * C + c0 + x];
    __syncthreads();
    #pragma unroll
    for (int j = 0; j < 32; j += 8)
        o[(size_t)(c0 + y + j) * R + r0 + x] = __float2half_rn(t[x][y + j]);
}

__global__ __launch_bounds__(256)
void softmax_h_kernel(const float* __restrict__ S, h16* __restrict__ P)
{
    __shared__ float buf[SEQ];
    __shared__ float red[256];
    const int tid = threadIdx.x;
    const float* p = S + (size_t)blockIdx.x * SEQ;
    float m = -INFINITY;
    for (int i = tid; i < SEQ; i += 256) { buf[i] = p[i]; m = fmaxf(m, p[i]); }
    red[tid] = m; __syncthreads();
    #pragma unroll
    for (int s = 128; s > 0; s >>= 1) {
        if (tid < s) red[tid] = fmaxf(red[tid], red[tid + s]);
        __syncthreads();
    }
    m = red[0]; __syncthreads();
    float sum = 0.f;
    for (int i = tid; i < SEQ; i += 256) {
        const float e = expf(buf[i] - m); buf[i] = e; sum += e;
    }
    red[tid] = sum; __syncthreads();
    #pragma unroll
    for (int s = 128; s > 0; s >>= 1) {
        if (tid < s) red[tid] += red[tid + s];
        __syncthreads();
    }
    const float inv = 1.f / red[0];
    h16* pp = P + (size_t)blockIdx.x * SEQ;
    for (int i = tid; i < SEQ; i += 256)
        pp[i] = __float2half_rn(buf[i] * inv);
}

extern "C" void kernel_launch(void* const* d_in, const int* in_sizes, int n_in,
                              void* d_out, int out_size)
{
    (void)in_sizes; (void)n_in; (void)out_size;
    const float* x  = (const float*)d_in[0];
    const float* W[3] = {(const float*)d_in[1], (const float*)d_in[3], (const float*)d_in[5]};
    const float* bq = (const float*)d_in[2];
    const float* bk = (const float*)d_in[4];
    const float* bv = (const float*)d_in[6];
    float* out = (float*)d_out;

    static bool init = false;
    static h16 *xp, *wp[3], *qp, *kp, *vtp, *pp;
    static float* Sp;
    if (!init) {
        cudaGetSymbolAddress((void**)&xp, g_x);
        h16* wb;
        cudaGetSymbolAddress((void**)&wb, g_w);
        for (int i = 0; i < 3; i++) wp[i] = wb + (size_t)i * EMB * EMB;
        cudaGetSymbolAddress((void**)&qp, g_q);
        cudaGetSymbolAddress((void**)&kp, g_k);
        cudaGetSymbolAddress((void**)&vtp, g_vt);
        cudaGetSymbolAddress((void**)&Sp, g_S);
        cudaGetSymbolAddress((void**)&pp, g_p);
        cudaFuncSetAttribute(gemm1<0>, cudaFuncAttributeMaxDynamicSharedMemorySize, DYN_SMEM);
        cudaFuncSetAttribute(gemm1<1>, cudaFuncAttributeMaxDynamicSharedMemorySize, DYN_SMEM);
        init = true;
    }

    // 1. convert x; convert+transpose W (W[K,N] -> Wt[N,K])
    cvt_kernel<<<1024, 256>>>(x, xp, (size_t)SEQ * EMB);
    for (int i = 0; i < 3; i++)
        cvtT_kernel<<<dim3(EMB / 32, EMB / 32), 256>>>(W[i], wp[i], EMB, EMB);

    const dim3 gP((SEQ / MT) * (EMB / NTB));   // 1024
    const dim3 gS((SEQ / MT) * (SEQ / NTB));   // 4096
    // 2. Q, K projections -> fp16 (bias fused)
    gemm1<1><<<gP, 256, DYN_SMEM>>>(xp, wp[0], EMB, EMB, bq, 1.f, nullptr, qp);
    gemm1<1><<<gP, 256, DYN_SMEM>>>(xp, wp[1], EMB, EMB, bk, 1.f, nullptr, kp);
    // 3. V projection -> fp32 tmp, then convert+transpose -> Vt[E,S]
    gemm1<0><<<gP, 256, DYN_SMEM>>>(xp, wp[2], EMB, EMB, bv, 1.f, Sp, nullptr);
    cvtT_kernel<<<dim3(EMB / 32, SEQ / 32), 256>>>(Sp, vtp, SEQ, EMB);
    // 4. S = Q @ K^T * 1/sqrt(E)
    gemm1<0><<<gS, 256, DYN_SMEM>>>(qp, kp, SEQ, EMB, nullptr,
                                    1.f / sqrtf((float)EMB), Sp, nullptr);
    // 5. softmax -> P fp16
    softmax_h_kernel<<<SEQ, 256>>>(Sp, pp);
    // 6. out = P @ Vt^T  (Vt is [E,S], so B^T = V)
    gemm1<0><<<gP, 256, DYN_SMEM>>>(pp, vtp, EMB, SEQ, nullptr, 1.f, out, nullptr);
}